// round 11
// baseline (speedup 1.0000x reference)
#include <cuda_runtime.h>
#include <cstdint>

// ---------------------------------------------------------------------------
// NeuralSpline R10 (resubmit; prior round was a broker/container infra
// failure with no harness output — same signature as rounds 5/6, which passed
// on identical-source resubmit).  conv32 restructured to 256 thr / 4-oc warps
// (8 accums per thread) to DOUBLE total warp count — R9 showed occupancy is
// set by per-thread work, not block shape.  cp.async fill + even/odd-split
// buffers unchanged from R9.
// ---------------------------------------------------------------------------

#define EPSF 1e-5f

static __device__ __align__(16) float g_buf1[64 * 32 * 127 * 128 + 64];
static __device__ __align__(16) float g_buf2[64 * 32 * 63 * 64 + 64];
static __device__ __align__(16) float g_buf3[64 * 32 * 31 * 32 + 64];
static __device__ __align__(16) float g_buf4[64 * 32 * 15 * 16 + 64];
static __device__ __align__(16) float g_buf5[64 * 32 * 7 * 8 + 64];
static __device__ __align__(16) float g_wt1[27 * 32];
static __device__ __align__(16) float g_wtl[4 * 288 * 32];
static __device__ float g_bns[5 * 32];
static __device__ float g_bsh[5 * 32];
static __device__ float g_coef[64 * 27];

// ---- packed f32x2 helpers ---------------------------------------------------
__device__ __forceinline__ unsigned long long pk2(float x) {
    unsigned long long r;
    unsigned u = __float_as_uint(x);
    asm("mov.b64 %0, {%1, %1};" : "=l"(r) : "r"(u));
    return r;
}
__device__ __forceinline__ void ffma2(unsigned long long& a, unsigned long long x,
                                      unsigned long long w) {
    asm("fma.rn.f32x2 %0, %1, %2, %0;" : "+l"(a) : "l"(x), "l"(w));
}
__device__ __forceinline__ float lo32(unsigned long long v) {
    return __uint_as_float((unsigned)(v & 0xffffffffULL));
}
__device__ __forceinline__ float hi32(unsigned long long v) {
    return __uint_as_float((unsigned)(v >> 32));
}
__device__ __forceinline__ uint32_t smem_u32(const void* p) {
    uint32_t a;
    asm("{ .reg .u64 t; cvta.to.shared.u64 t, %1; cvt.u32.u64 %0, t; }" : "=r"(a) : "l"(p));
    return a;
}
__device__ __forceinline__ void cp16(uint32_t dst, const void* src) {
    asm volatile("cp.async.cg.shared.global [%0], [%1], 16;" :: "r"(dst), "l"(src));
}

// ---------------------------------------------------------------------------
__global__ void prep_kernel(const float* __restrict__ c1w, const float* __restrict__ cw,
                            const float* __restrict__ bng, const float* __restrict__ bnb,
                            const float* __restrict__ bnm, const float* __restrict__ bnv) {
    const int stride = gridDim.x * blockDim.x;
    const int t0 = blockIdx.x * blockDim.x + threadIdx.x;
    for (int i = t0; i < 5 * 32; i += stride) {
        float inv = bng[i] * rsqrtf(bnv[i] + EPSF);
        g_bns[i] = inv;
        g_bsh[i] = bnb[i] - bnm[i] * inv;
    }
    for (int i = t0; i < 27 * 32; i += stride) {
        int oc = i / 27, r = i % 27;
        g_wt1[r * 32 + oc] = c1w[i];
    }
    for (int i = t0; i < 4 * 32 * 288; i += stride) {
        int l = i / 9216, rem = i % 9216;
        int oc = rem / 288, r = rem % 288;
        g_wtl[l * 9216 + r * 32 + oc] = cw[i];
    }
}

// 48 FFMA2 per (ic,kh) row unit, 8-oc version (conv1).
__device__ __forceinline__ void conv_row_taps8(unsigned long long (&acc)[16],
                                               const float4 ev, const float e4,
                                               const float4 od,
                                               const float* __restrict__ pw) {
    unsigned long long pe0 = pk2(ev.x), pe1 = pk2(ev.y), pe2 = pk2(ev.z),
                       pe3 = pk2(ev.w), pe4 = pk2(e4);
    unsigned long long po0 = pk2(od.x), po1 = pk2(od.y), po2 = pk2(od.z), po3 = pk2(od.w);
#pragma unroll
    for (int kw = 0; kw < 3; kw++) {
        unsigned long long x0, x1, x2, x3;
        if (kw == 0) { x0 = pe0; x1 = pe1; x2 = pe2; x3 = pe3; }
        else if (kw == 1) { x0 = po0; x1 = po1; x2 = po2; x3 = po3; }
        else { x0 = pe1; x1 = pe2; x2 = pe3; x3 = pe4; }
        const ulonglong2* w2 = reinterpret_cast<const ulonglong2*>(pw + kw * 32);
        ulonglong2 wa = w2[0], wb = w2[1];
        ffma2(acc[0], x0, wa.x);  ffma2(acc[1], x0, wa.y);
        ffma2(acc[2], x0, wb.x);  ffma2(acc[3], x0, wb.y);
        ffma2(acc[4], x1, wa.x);  ffma2(acc[5], x1, wa.y);
        ffma2(acc[6], x1, wb.x);  ffma2(acc[7], x1, wb.y);
        ffma2(acc[8], x2, wa.x);  ffma2(acc[9], x2, wa.y);
        ffma2(acc[10], x2, wb.x); ffma2(acc[11], x2, wb.y);
        ffma2(acc[12], x3, wa.x); ffma2(acc[13], x3, wa.y);
        ffma2(acc[14], x3, wb.x); ffma2(acc[15], x3, wb.y);
    }
}

// 24 FFMA2 per (ic,kh) row unit, 4-oc version (conv32 R10).
__device__ __forceinline__ void conv_row_taps4(unsigned long long (&acc)[8],
                                               const float4 ev, const float e4,
                                               const float4 od,
                                               const float* __restrict__ pw) {
    unsigned long long pe0 = pk2(ev.x), pe1 = pk2(ev.y), pe2 = pk2(ev.z),
                       pe3 = pk2(ev.w), pe4 = pk2(e4);
    unsigned long long po0 = pk2(od.x), po1 = pk2(od.y), po2 = pk2(od.z), po3 = pk2(od.w);
#pragma unroll
    for (int kw = 0; kw < 3; kw++) {
        unsigned long long x0, x1, x2, x3;
        if (kw == 0) { x0 = pe0; x1 = pe1; x2 = pe2; x3 = pe3; }
        else if (kw == 1) { x0 = po0; x1 = po1; x2 = po2; x3 = po3; }
        else { x0 = pe1; x1 = pe2; x2 = pe3; x3 = pe4; }
        const ulonglong2* w2 = reinterpret_cast<const ulonglong2*>(pw + kw * 32);
        ulonglong2 wa = w2[0];
        ffma2(acc[0], x0, wa.x); ffma2(acc[1], x0, wa.y);
        ffma2(acc[2], x1, wa.x); ffma2(acc[3], x1, wa.y);
        ffma2(acc[4], x2, wa.x); ffma2(acc[5], x2, wa.y);
        ffma2(acc[6], x3, wa.x); ffma2(acc[7], x3, wa.y);
    }
}

// ---------------------------------------------------------------------------
// conv1: 3 -> 32 ch, 255x255 -> 127 x (64e|63o).  16x16 tile, 256 thr.
// ---------------------------------------------------------------------------
__global__ void __launch_bounds__(256) conv1_kernel(const float* __restrict__ in,
                                                    const float* __restrict__ bias) {
    __shared__ __align__(16) float s_in[3 * 33 * 40];
    __shared__ __align__(16) float s_w[27 * 32];
    const int b = blockIdx.y;
    const int tx = blockIdx.x & 7, ty = blockIdx.x >> 3;
    const int ox0t = tx * 16, oy0 = ty * 16;
    const int ix0 = 2 * ox0t, iy0 = 2 * oy0;

    if (threadIdx.x < 216)
        reinterpret_cast<float4*>(s_w)[threadIdx.x] =
            reinterpret_cast<const float4*>(g_wt1)[threadIdx.x];

    const float* inb = in + (size_t)b * 3 * 65025;
    int goff[5], soff[5];
#pragma unroll
    for (int k = 0; k < 5; k++) {
        int s = threadIdx.x + k * 256;
        s = min(s, 1088);
        int yy = s / 33, xx = s - yy * 33;
        int gy = min(iy0 + yy, 254), gx = min(ix0 + xx, 254);
        goff[k] = gy * 255 + gx;
        soff[k] = yy * 40 + ((xx & 1) ? 20 + (xx >> 1) : (xx >> 1));
    }
#pragma unroll
    for (int ic = 0; ic < 3; ic++) {
        float v[5];
#pragma unroll
        for (int k = 0; k < 5; k++) v[k] = inb[ic * 65025 + goff[k]];
#pragma unroll
        for (int k = 0; k < 5; k++) s_in[ic * 1320 + soff[k]] = v[k];
    }
    __syncthreads();

    const int xg = threadIdx.x & 3;
    const int y = (threadIdx.x >> 2) & 15;
    const int g = threadIdx.x >> 6;
    unsigned long long acc[16];
#pragma unroll
    for (int i = 0; i < 16; i++) acc[i] = 0ULL;

    const float* pw0 = s_w + g * 8;
#pragma unroll
    for (int ic = 0; ic < 3; ic++) {
        const float* prb = s_in + ic * 1320 + (2 * y) * 40 + 4 * xg;
#pragma unroll
        for (int kh = 0; kh < 3; kh++) {
            const float* pr = prb + kh * 40;
            float4 ev = *reinterpret_cast<const float4*>(pr);
            float e4 = pr[4];
            float4 od = *reinterpret_cast<const float4*>(pr + 20);
            conv_row_taps8(acc, ev, e4, od, pw0 + (ic * 9 + kh * 3) * 32);
        }
    }

    const int oy = oy0 + y;
    const int ox0 = ox0t + 4 * xg;
    if (oy < 127 && ox0 < 128) {
        float* op = g_buf1 + ((size_t)b * 32 + g * 8) * (127 * 128) + (size_t)oy * 128 + (ox0 >> 1);
#pragma unroll
        for (int j = 0; j < 4; j++) {
            int oc0 = g * 8 + 2 * j;
            float bi0 = bias[oc0], sc0 = g_bns[oc0], sh0 = g_bsh[oc0];
            float bi1 = bias[oc0 + 1], sc1 = g_bns[oc0 + 1], sh1 = g_bsh[oc0 + 1];
            float t0 = fmaxf(lo32(acc[0 + j]) + bi0, 0.f) * sc0 + sh0;
            float t1 = fmaxf(lo32(acc[4 + j]) + bi0, 0.f) * sc0 + sh0;
            float t2 = fmaxf(lo32(acc[8 + j]) + bi0, 0.f) * sc0 + sh0;
            float t3 = fmaxf(lo32(acc[12 + j]) + bi0, 0.f) * sc0 + sh0;
            float u0 = fmaxf(hi32(acc[0 + j]) + bi1, 0.f) * sc1 + sh1;
            float u1 = fmaxf(hi32(acc[4 + j]) + bi1, 0.f) * sc1 + sh1;
            float u2 = fmaxf(hi32(acc[8 + j]) + bi1, 0.f) * sc1 + sh1;
            float u3 = fmaxf(hi32(acc[12 + j]) + bi1, 0.f) * sc1 + sh1;
            float* p0 = op + (size_t)(2 * j) * (127 * 128);
            float* p1 = op + (size_t)(2 * j + 1) * (127 * 128);
            *reinterpret_cast<float2*>(p0) = make_float2(t0, t2);
            *reinterpret_cast<float2*>(p0 + 64) = make_float2(t1, t3);
            *reinterpret_cast<float2*>(p1) = make_float2(u0, u2);
            *reinterpret_cast<float2*>(p1 + 64) = make_float2(u1, u3);
        }
    }
}

// ---------------------------------------------------------------------------
// conv2..5: 32 -> 32 ch.  256 thr (xg4 x y8 x g8, 4 oc per warp), 16x8 tile,
// 4-ic x 8 phases, cp.async double-buffered fill.
// ---------------------------------------------------------------------------
template <int L, int IH, int IWS, int IE, int OH, int OWS, int OE, int TX>
__global__ void __launch_bounds__(256, 4) conv32_kernel(const float* __restrict__ bias) {
    constexpr int SW_FL = 4 * 680;            // 2720 floats input region
    constexpr int BUF_FL = SW_FL + 1152;      // + weights = 3872 floats
    constexpr unsigned BUF_B = BUF_FL * 4u;
    constexpr unsigned IN_STEPB = 4u * IH * IWS * 4u;

    __shared__ __align__(16) float smem[2 * BUF_FL];

    const int b = blockIdx.y;
    const int tx = blockIdx.x % TX, ty = blockIdx.x / TX;
    const int ox0t = tx * 16, oy0 = ty * 8;
    const int ix0 = 2 * ox0t, iy0 = 2 * oy0;
    const float* in = (L == 0) ? g_buf1 : (L == 1) ? g_buf2 : (L == 2) ? g_buf3 : g_buf4;
    float* out = (L == 0) ? g_buf2 : (L == 1) ? g_buf3 : (L == 2) ? g_buf4 : g_buf5;
    const char* inb8 = (const char*)(in + (size_t)b * 32 * IH * IWS);
    const char* wt8 = (const char*)(g_wtl + L * 9216);

    // fill slots: 3 input (612 float4) + 2 weight (288 float4) over 256 thr
    unsigned in_src[3], in_dst[3], w_src[2], w_dst[2];
    bool vin[3], vw[2];
#pragma unroll
    for (int k = 0; k < 3; k++) {
        int s = threadIdx.x + k * 256;
        vin[k] = (s < 612);
        s = min(s, 611);
        int ic = s / 153, r = s - ic * 153;
        int row = r / 9, xq = r - row * 9;
        int gy = min(iy0 + row, IH - 1);
        int half = (xq < 5) ? ((ix0 >> 1) + 4 * xq) : (IE + (ix0 >> 1) + 4 * (xq - 5));
        in_src[k] = (unsigned)((ic * IH + gy) * IWS + half) * 4u;
        in_dst[k] = (unsigned)(ic * 680 + row * 40 + ((xq < 5) ? 4 * xq : 20 + 4 * (xq - 5))) * 4u;
    }
#pragma unroll
    for (int k = 0; k < 2; k++) {
        int idx = threadIdx.x + k * 256;
        vw[k] = (idx < 288);
        idx = min(idx, 287);
        w_src[k] = (unsigned)idx * 16u;
        w_dst[k] = (unsigned)(SW_FL * 4) + (unsigned)idx * 16u;
    }
    const uint32_t sb = smem_u32(smem);

    const int xg = threadIdx.x & 3;
    const int y = (threadIdx.x >> 2) & 7;
    const int g = threadIdx.x >> 5; // 0..7, 4 oc each; warp == group
    unsigned long long acc[8];
#pragma unroll
    for (int i = 0; i < 8; i++) acc[i] = 0ULL;

    // prologue fill(0)
    {
        uint32_t base = sb;
#pragma unroll
        for (int k = 0; k < 3; k++) if (vin[k]) cp16(base + in_dst[k], inb8 + in_src[k]);
#pragma unroll
        for (int k = 0; k < 2; k++) if (vw[k]) cp16(base + w_dst[k], wt8 + w_src[k]);
        asm volatile("cp.async.commit_group;");
    }

    for (int ph = 0; ph < 8; ph++) {
        if (ph < 7) {
            uint32_t base = sb + (unsigned)((ph + 1) & 1) * BUF_B;
            unsigned io = (unsigned)(ph + 1) * IN_STEPB;
            unsigned wo = (unsigned)(ph + 1) * 4608u;
#pragma unroll
            for (int k = 0; k < 3; k++) if (vin[k]) cp16(base + in_dst[k], inb8 + in_src[k] + io);
#pragma unroll
            for (int k = 0; k < 2; k++) if (vw[k]) cp16(base + w_dst[k], wt8 + w_src[k] + wo);
            asm volatile("cp.async.commit_group;");
            asm volatile("cp.async.wait_group 1;");
        } else {
            asm volatile("cp.async.wait_group 0;");
        }
        __syncthreads();

        const float* sbf = smem + (ph & 1) * BUF_FL;
        const float* pw0 = sbf + SW_FL + g * 4;
#pragma unroll
        for (int ic = 0; ic < 4; ic++) {
            const float* prb = sbf + ic * 680 + (2 * y) * 40 + 4 * xg;
            const float* pw1 = pw0 + ic * 288;
#pragma unroll
            for (int kh = 0; kh < 3; kh++) {
                const float* pr = prb + kh * 40;
                float4 ev = *reinterpret_cast<const float4*>(pr);
                float e4 = pr[4];
                float4 od = *reinterpret_cast<const float4*>(pr + 20);
                conv_row_taps4(acc, ev, e4, od, pw1 + kh * 96);
            }
        }
        __syncthreads(); // readers done before buf refilled next phase
    }

    const int oy = oy0 + y;
    const int ox0 = ox0t + 4 * xg;
    // ox0 < OWS is load-bearing: padding lanes of the 7-wide layer would
    // otherwise clobber odd-half/next-row data (the R8 bug).
    if (oy < OH && ox0 < OWS) {
        const float* bns = g_bns + (L + 1) * 32;
        const float* bsh = g_bsh + (L + 1) * 32;
        float* op = out + ((size_t)b * 32 + g * 4) * (OH * OWS) + (size_t)oy * OWS + (ox0 >> 1);
#pragma unroll
        for (int j = 0; j < 2; j++) {
            int oc0 = g * 4 + 2 * j;
            float bi0 = bias[oc0], sc0 = bns[oc0], sh0 = bsh[oc0];
            float bi1 = bias[oc0 + 1], sc1 = bns[oc0 + 1], sh1 = bsh[oc0 + 1];
            float t0 = fmaxf(lo32(acc[0 + j]) + bi0, 0.f) * sc0 + sh0;  // x+0 even
            float t1 = fmaxf(lo32(acc[2 + j]) + bi0, 0.f) * sc0 + sh0;  // x+1 odd
            float t2 = fmaxf(lo32(acc[4 + j]) + bi0, 0.f) * sc0 + sh0;  // x+2 even
            float t3 = fmaxf(lo32(acc[6 + j]) + bi0, 0.f) * sc0 + sh0;  // x+3 odd
            float u0 = fmaxf(hi32(acc[0 + j]) + bi1, 0.f) * sc1 + sh1;
            float u1 = fmaxf(hi32(acc[2 + j]) + bi1, 0.f) * sc1 + sh1;
            float u2 = fmaxf(hi32(acc[4 + j]) + bi1, 0.f) * sc1 + sh1;
            float u3 = fmaxf(hi32(acc[6 + j]) + bi1, 0.f) * sc1 + sh1;
            float* p0 = op + (size_t)(2 * j) * (OH * OWS);
            float* p1 = op + (size_t)(2 * j + 1) * (OH * OWS);
            *reinterpret_cast<float2*>(p0) = make_float2(t0, t2);
            *reinterpret_cast<float2*>(p0 + OE) = make_float2(t1, t3);
            *reinterpret_cast<float2*>(p1) = make_float2(u0, u2);
            *reinterpret_cast<float2*>(p1 + OE) = make_float2(u1, u3);
        }
    }
}

// ---------------------------------------------------------------------------
// FC(1568->20 relu) -> FC(20->10) -> Thomas tridiagonal solve (fp64) -> a,b,c.
// buf5 rows are even/odd-split: (row,x) -> row*8 + (x&1 ? 4+x/2 : x/2).
// ---------------------------------------------------------------------------
__global__ void __launch_bounds__(256) fc_kernel(const float* __restrict__ l1w,
                                                 const float* __restrict__ l1b,
                                                 const float* __restrict__ l2w,
                                                 const float* __restrict__ l2b) {
    __shared__ float s_y[1568];
    __shared__ float s_h1[20];
    __shared__ float s_ys[10];
    const int b = blockIdx.x;
    const float* yb = g_buf5 + (size_t)b * 32 * 7 * 8;
    for (int i = threadIdx.x; i < 1568; i += 256) {
        int oc = i / 49, r = i % 49;
        int row = r / 7, x = r - row * 7;
        int pos = row * 8 + ((x & 1) ? 4 + (x >> 1) : (x >> 1));
        s_y[i] = yb[oc * 56 + pos];
    }
    __syncthreads();

    const int warp = threadIdx.x >> 5, lane = threadIdx.x & 31;
    for (int j = warp; j < 20; j += 8) {
        float s = 0.f;
        const float* w = l1w + (size_t)j * 1568;
        for (int k = lane; k < 1568; k += 32) s += s_y[k] * w[k];
#pragma unroll
        for (int o = 16; o > 0; o >>= 1) s += __shfl_down_sync(0xffffffffu, s, o);
        if (lane == 0) s_h1[j] = fmaxf(s + l1b[j], 0.f);
    }
    __syncthreads();

    if (threadIdx.x < 10) {
        float s = l2b[threadIdx.x];
        const float* w = l2w + threadIdx.x * 20;
#pragma unroll
        for (int j = 0; j < 20; j++) s += s_h1[j] * w[j];
        s_ys[threadIdx.x] = s;
    }
    __syncthreads();

    if (threadIdx.x == 0) {
        const double h = 1.0 / 9.0;
        double ys[10];
#pragma unroll
        for (int i = 0; i < 10; i++) ys[i] = (double)s_ys[i];
        double d[8], cp[8];
        for (int i = 0; i < 8; i++)
            d[i] = (6.0 / (h * h)) * (ys[i + 2] - 2.0 * ys[i + 1] + ys[i]);
        cp[0] = 0.25;
        d[0] *= 0.25;
        for (int i = 1; i < 8; i++) {
            double m = 4.0 - cp[i - 1];
            cp[i] = 1.0 / m;
            d[i] = (d[i] - d[i - 1]) / m;
        }
        double M[10];
        M[0] = 0.0;
        M[9] = 0.0;
        M[8] = d[7];
        for (int i = 6; i >= 0; i--) M[i + 1] = d[i] - cp[i] * M[i + 2];
        float* cf = g_coef + b * 27;
        for (int i = 0; i < 9; i++) {
            cf[i] = (float)((M[i + 1] - M[i]) / (6.0 * h));
            cf[9 + i] = (float)(M[i] * 0.5);
            cf[18 + i] = (float)((ys[i + 1] - ys[i]) / h - (M[i + 1] + 2.0 * M[i]) * (h / 6.0));
        }
    }
}

// ---------------------------------------------------------------------------
// eval: fast bucket via x*9; exact __fdiv_rn fallback only near knots.
// ---------------------------------------------------------------------------
__device__ __forceinline__ float evalpix(float x, const float* __restrict__ sc) {
    const float h = 1.0f / 9.0f;
    float tf = fminf(fmaxf(x * 9.0f, 0.f), 8.f);
    int xi = (int)tf;
    float fr = tf - (float)xi;
    if (fr < 1e-4f || fr > 0.9999f) {
        float te = fminf(fmaxf(__fdiv_rn(x, h), 0.f), 8.f);
        xi = (int)te;
    }
    float xf = x - (float)xi * h;
    return ((sc[xi] * xf + sc[9 + xi]) * xf + sc[18 + xi]) * xf;
}

__global__ void __launch_bounds__(256) eval_kernel(const float* __restrict__ in,
                                                   float* __restrict__ out) {
    __shared__ float s_c[27];
    const int b = blockIdx.y;
    if (threadIdx.x < 27) s_c[threadIdx.x] = g_coef[b * 27 + threadIdx.x];
    __syncthreads();
    const int N = 3 * 255 * 255;
    const float* ib = in + (size_t)b * N;
    float* ob = out + (size_t)b * N;
    const int mis = (4 - ((3 * b) & 3)) & 3;
    const int nv = (N - mis) >> 2;
    const float4* iv = reinterpret_cast<const float4*>(ib + mis);
    float4* ov = reinterpret_cast<float4*>(ob + mis);
    for (int v = blockIdx.x * 256 + threadIdx.x; v < nv; v += gridDim.x * 256) {
        float4 x = iv[v];
        float4 r;
        r.x = evalpix(x.x, s_c);
        r.y = evalpix(x.y, s_c);
        r.z = evalpix(x.z, s_c);
        r.w = evalpix(x.w, s_c);
        ov[v] = r;
    }
    const int tail = N - mis - 4 * nv;
    if (blockIdx.x == 0 && threadIdx.x < mis + tail) {
        int t = threadIdx.x;
        int i = (t < mis) ? t : (mis + 4 * nv + (t - mis));
        ob[i] = evalpix(ib[i], s_c);
    }
}

// ---------------------------------------------------------------------------
extern "C" void kernel_launch(void* const* d_in, const int* in_sizes, int n_in,
                              void* d_out, int out_size) {
    const float* batch = (const float*)d_in[0];
    const float* c1w = (const float*)d_in[1];
    const float* c1b = (const float*)d_in[2];
    const float* cw = (const float*)d_in[3];
    const float* cb = (const float*)d_in[4];
    const float* bng = (const float*)d_in[5];
    const float* bnb = (const float*)d_in[6];
    const float* bnm = (const float*)d_in[7];
    const float* bnv = (const float*)d_in[8];
    const float* l1w = (const float*)d_in[9];
    const float* l1b = (const float*)d_in[10];
    const float* l2w = (const float*)d_in[11];
    const float* l2b = (const float*)d_in[12];
    float* out = (float*)d_out;

    prep_kernel<<<64, 256>>>(c1w, cw, bng, bnb, bnm, bnv);
    conv1_kernel<<<dim3(64, 64), 256>>>(batch, c1b);
    //            L  IH  IWS IE  OH  OWS OE  TX
    conv32_kernel<0, 127, 128, 64, 63, 64, 32, 4><<<dim3(32, 64), 256>>>(cb + 0);
    conv32_kernel<1, 63, 64, 32, 31, 32, 16, 2><<<dim3(8, 64), 256>>>(cb + 32);
    conv32_kernel<2, 31, 32, 16, 15, 16, 8, 1><<<dim3(2, 64), 256>>>(cb + 64);
    conv32_kernel<3, 15, 16, 8, 7, 8, 4, 1><<<dim3(1, 64), 256>>>(cb + 96);
    fc_kernel<<<64, 256>>>(l1w, l1b, l2w, l2b);
    eval_kernel<<<dim3(191, 64), 256>>>(batch, out);
}

// round 12
// speedup vs baseline: 1.0538x; 1.0538x over previous
#include <cuda_runtime.h>
#include <cstdint>

// ---------------------------------------------------------------------------
// NeuralSpline R12: conv32 with 16-oc x 4-spatial per thread (32 accums) to
// maximize FFMA2 per crossbar wavefront (R10 proved occupancy is NOT the
// limiter; arithmetic intensity per LDS is).  16x16 tiles, 2-ic x 16 phases
// (static-smem limit), cp.async double-buffer + even/odd-split buffers (R9).
// ---------------------------------------------------------------------------

#define EPSF 1e-5f

static __device__ __align__(16) float g_buf1[64 * 32 * 127 * 128 + 64];
static __device__ __align__(16) float g_buf2[64 * 32 * 63 * 64 + 64];
static __device__ __align__(16) float g_buf3[64 * 32 * 31 * 32 + 64];
static __device__ __align__(16) float g_buf4[64 * 32 * 15 * 16 + 64];
static __device__ __align__(16) float g_buf5[64 * 32 * 7 * 8 + 64];
static __device__ __align__(16) float g_wt1[27 * 32];
static __device__ __align__(16) float g_wtl[4 * 288 * 32];
static __device__ float g_bns[5 * 32];
static __device__ float g_bsh[5 * 32];
static __device__ float g_coef[64 * 27];

// ---- packed f32x2 helpers ---------------------------------------------------
__device__ __forceinline__ unsigned long long pk2(float x) {
    unsigned long long r;
    unsigned u = __float_as_uint(x);
    asm("mov.b64 %0, {%1, %1};" : "=l"(r) : "r"(u));
    return r;
}
__device__ __forceinline__ void ffma2(unsigned long long& a, unsigned long long x,
                                      unsigned long long w) {
    asm("fma.rn.f32x2 %0, %1, %2, %0;" : "+l"(a) : "l"(x), "l"(w));
}
__device__ __forceinline__ float lo32(unsigned long long v) {
    return __uint_as_float((unsigned)(v & 0xffffffffULL));
}
__device__ __forceinline__ float hi32(unsigned long long v) {
    return __uint_as_float((unsigned)(v >> 32));
}
__device__ __forceinline__ uint32_t smem_u32(const void* p) {
    uint32_t a;
    asm("{ .reg .u64 t; cvta.to.shared.u64 t, %1; cvt.u32.u64 %0, t; }" : "=r"(a) : "l"(p));
    return a;
}
__device__ __forceinline__ void cp16(uint32_t dst, const void* src) {
    asm volatile("cp.async.cg.shared.global [%0], [%1], 16;" :: "r"(dst), "l"(src));
}

// ---------------------------------------------------------------------------
__global__ void prep_kernel(const float* __restrict__ c1w, const float* __restrict__ cw,
                            const float* __restrict__ bng, const float* __restrict__ bnb,
                            const float* __restrict__ bnm, const float* __restrict__ bnv) {
    const int stride = gridDim.x * blockDim.x;
    const int t0 = blockIdx.x * blockDim.x + threadIdx.x;
    for (int i = t0; i < 5 * 32; i += stride) {
        float inv = bng[i] * rsqrtf(bnv[i] + EPSF);
        g_bns[i] = inv;
        g_bsh[i] = bnb[i] - bnm[i] * inv;
    }
    for (int i = t0; i < 27 * 32; i += stride) {
        int oc = i / 27, r = i % 27;
        g_wt1[r * 32 + oc] = c1w[i];
    }
    for (int i = t0; i < 4 * 32 * 288; i += stride) {
        int l = i / 9216, rem = i % 9216;
        int oc = rem / 288, r = rem % 288;
        g_wtl[l * 9216 + r * 32 + oc] = cw[i];
    }
}

// 48 FFMA2 per (ic,kh) row unit, 8-oc version (conv1).
__device__ __forceinline__ void conv_row_taps8(unsigned long long (&acc)[16],
                                               const float4 ev, const float e4,
                                               const float4 od,
                                               const float* __restrict__ pw) {
    unsigned long long pe0 = pk2(ev.x), pe1 = pk2(ev.y), pe2 = pk2(ev.z),
                       pe3 = pk2(ev.w), pe4 = pk2(e4);
    unsigned long long po0 = pk2(od.x), po1 = pk2(od.y), po2 = pk2(od.z), po3 = pk2(od.w);
#pragma unroll
    for (int kw = 0; kw < 3; kw++) {
        unsigned long long x0, x1, x2, x3;
        if (kw == 0) { x0 = pe0; x1 = pe1; x2 = pe2; x3 = pe3; }
        else if (kw == 1) { x0 = po0; x1 = po1; x2 = po2; x3 = po3; }
        else { x0 = pe1; x1 = pe2; x2 = pe3; x3 = pe4; }
        const ulonglong2* w2 = reinterpret_cast<const ulonglong2*>(pw + kw * 32);
        ulonglong2 wa = w2[0], wb = w2[1];
        ffma2(acc[0], x0, wa.x);  ffma2(acc[1], x0, wa.y);
        ffma2(acc[2], x0, wb.x);  ffma2(acc[3], x0, wb.y);
        ffma2(acc[4], x1, wa.x);  ffma2(acc[5], x1, wa.y);
        ffma2(acc[6], x1, wb.x);  ffma2(acc[7], x1, wb.y);
        ffma2(acc[8], x2, wa.x);  ffma2(acc[9], x2, wa.y);
        ffma2(acc[10], x2, wb.x); ffma2(acc[11], x2, wb.y);
        ffma2(acc[12], x3, wa.x); ffma2(acc[13], x3, wa.y);
        ffma2(acc[14], x3, wb.x); ffma2(acc[15], x3, wb.y);
    }
}

// 96 FFMA2 per (ic,kh) row unit, 16-oc version (conv32 R12).
__device__ __forceinline__ void conv_row_taps16(unsigned long long (&acc)[32],
                                                const float4 ev, const float e4,
                                                const float4 od,
                                                const float* __restrict__ pw) {
    unsigned long long pe0 = pk2(ev.x), pe1 = pk2(ev.y), pe2 = pk2(ev.z),
                       pe3 = pk2(ev.w), pe4 = pk2(e4);
    unsigned long long po0 = pk2(od.x), po1 = pk2(od.y), po2 = pk2(od.z), po3 = pk2(od.w);
#pragma unroll
    for (int kw = 0; kw < 3; kw++) {
        unsigned long long x0, x1, x2, x3;
        if (kw == 0) { x0 = pe0; x1 = pe1; x2 = pe2; x3 = pe3; }
        else if (kw == 1) { x0 = po0; x1 = po1; x2 = po2; x3 = po3; }
        else { x0 = pe1; x1 = pe2; x2 = pe3; x3 = pe4; }
        const ulonglong2* w2 = reinterpret_cast<const ulonglong2*>(pw + kw * 32);
        ulonglong2 wa = w2[0], wb = w2[1], wc = w2[2], wd = w2[3];
        ffma2(acc[0], x0, wa.x);  ffma2(acc[1], x0, wa.y);
        ffma2(acc[2], x0, wb.x);  ffma2(acc[3], x0, wb.y);
        ffma2(acc[4], x0, wc.x);  ffma2(acc[5], x0, wc.y);
        ffma2(acc[6], x0, wd.x);  ffma2(acc[7], x0, wd.y);
        ffma2(acc[8], x1, wa.x);  ffma2(acc[9], x1, wa.y);
        ffma2(acc[10], x1, wb.x); ffma2(acc[11], x1, wb.y);
        ffma2(acc[12], x1, wc.x); ffma2(acc[13], x1, wc.y);
        ffma2(acc[14], x1, wd.x); ffma2(acc[15], x1, wd.y);
        ffma2(acc[16], x2, wa.x); ffma2(acc[17], x2, wa.y);
        ffma2(acc[18], x2, wb.x); ffma2(acc[19], x2, wb.y);
        ffma2(acc[20], x2, wc.x); ffma2(acc[21], x2, wc.y);
        ffma2(acc[22], x2, wd.x); ffma2(acc[23], x2, wd.y);
        ffma2(acc[24], x3, wa.x); ffma2(acc[25], x3, wa.y);
        ffma2(acc[26], x3, wb.x); ffma2(acc[27], x3, wb.y);
        ffma2(acc[28], x3, wc.x); ffma2(acc[29], x3, wc.y);
        ffma2(acc[30], x3, wd.x); ffma2(acc[31], x3, wd.y);
    }
}

// ---------------------------------------------------------------------------
// conv1: 3 -> 32 ch, 255x255 -> 127 x (64e|63o).  16x16 tile, 256 thr (R9).
// ---------------------------------------------------------------------------
__global__ void __launch_bounds__(256) conv1_kernel(const float* __restrict__ in,
                                                    const float* __restrict__ bias) {
    __shared__ __align__(16) float s_in[3 * 33 * 40];
    __shared__ __align__(16) float s_w[27 * 32];
    const int b = blockIdx.y;
    const int tx = blockIdx.x & 7, ty = blockIdx.x >> 3;
    const int ox0t = tx * 16, oy0 = ty * 16;
    const int ix0 = 2 * ox0t, iy0 = 2 * oy0;

    if (threadIdx.x < 216)
        reinterpret_cast<float4*>(s_w)[threadIdx.x] =
            reinterpret_cast<const float4*>(g_wt1)[threadIdx.x];

    const float* inb = in + (size_t)b * 3 * 65025;
    int goff[5], soff[5];
#pragma unroll
    for (int k = 0; k < 5; k++) {
        int s = threadIdx.x + k * 256;
        s = min(s, 1088);
        int yy = s / 33, xx = s - yy * 33;
        int gy = min(iy0 + yy, 254), gx = min(ix0 + xx, 254);
        goff[k] = gy * 255 + gx;
        soff[k] = yy * 40 + ((xx & 1) ? 20 + (xx >> 1) : (xx >> 1));
    }
#pragma unroll
    for (int ic = 0; ic < 3; ic++) {
        float v[5];
#pragma unroll
        for (int k = 0; k < 5; k++) v[k] = inb[ic * 65025 + goff[k]];
#pragma unroll
        for (int k = 0; k < 5; k++) s_in[ic * 1320 + soff[k]] = v[k];
    }
    __syncthreads();

    const int xg = threadIdx.x & 3;
    const int y = (threadIdx.x >> 2) & 15;
    const int g = threadIdx.x >> 6;
    unsigned long long acc[16];
#pragma unroll
    for (int i = 0; i < 16; i++) acc[i] = 0ULL;

    const float* pw0 = s_w + g * 8;
#pragma unroll
    for (int ic = 0; ic < 3; ic++) {
        const float* prb = s_in + ic * 1320 + (2 * y) * 40 + 4 * xg;
#pragma unroll
        for (int kh = 0; kh < 3; kh++) {
            const float* pr = prb + kh * 40;
            float4 ev = *reinterpret_cast<const float4*>(pr);
            float e4 = pr[4];
            float4 od = *reinterpret_cast<const float4*>(pr + 20);
            conv_row_taps8(acc, ev, e4, od, pw0 + (ic * 9 + kh * 3) * 32);
        }
    }

    const int oy = oy0 + y;
    const int ox0 = ox0t + 4 * xg;
    if (oy < 127 && ox0 < 128) {
        float* op = g_buf1 + ((size_t)b * 32 + g * 8) * (127 * 128) + (size_t)oy * 128 + (ox0 >> 1);
#pragma unroll
        for (int j = 0; j < 4; j++) {
            int oc0 = g * 8 + 2 * j;
            float bi0 = bias[oc0], sc0 = g_bns[oc0], sh0 = g_bsh[oc0];
            float bi1 = bias[oc0 + 1], sc1 = g_bns[oc0 + 1], sh1 = g_bsh[oc0 + 1];
            float t0 = fmaxf(lo32(acc[0 + j]) + bi0, 0.f) * sc0 + sh0;
            float t1 = fmaxf(lo32(acc[4 + j]) + bi0, 0.f) * sc0 + sh0;
            float t2 = fmaxf(lo32(acc[8 + j]) + bi0, 0.f) * sc0 + sh0;
            float t3 = fmaxf(lo32(acc[12 + j]) + bi0, 0.f) * sc0 + sh0;
            float u0 = fmaxf(hi32(acc[0 + j]) + bi1, 0.f) * sc1 + sh1;
            float u1 = fmaxf(hi32(acc[4 + j]) + bi1, 0.f) * sc1 + sh1;
            float u2 = fmaxf(hi32(acc[8 + j]) + bi1, 0.f) * sc1 + sh1;
            float u3 = fmaxf(hi32(acc[12 + j]) + bi1, 0.f) * sc1 + sh1;
            float* p0 = op + (size_t)(2 * j) * (127 * 128);
            float* p1 = op + (size_t)(2 * j + 1) * (127 * 128);
            *reinterpret_cast<float2*>(p0) = make_float2(t0, t2);
            *reinterpret_cast<float2*>(p0 + 64) = make_float2(t1, t3);
            *reinterpret_cast<float2*>(p1) = make_float2(u0, u2);
            *reinterpret_cast<float2*>(p1 + 64) = make_float2(u1, u3);
        }
    }
}

// ---------------------------------------------------------------------------
// conv2..5: 32 -> 32 ch.  128 thr (xg4 x y16 x g2: 16 oc x 4 sp per thread),
// 16x16 tile, 2-ic x 16 phases, cp.async double-buffered fill.
// ---------------------------------------------------------------------------
template <int L, int IH, int IWS, int IE, int OH, int OWS, int OE, int TX>
__global__ void __launch_bounds__(128, 4) conv32_kernel(const float* __restrict__ bias) {
    constexpr int SW_FL = 2 * 1320;           // input region: 2 ic x 33 rows x 40
    constexpr int BUF_FL = SW_FL + 576;       // + weights (2 ic x 288) = 3216
    constexpr unsigned BUF_B = BUF_FL * 4u;
    constexpr unsigned IN_STEPB = 2u * IH * IWS * 4u; // bytes per 2-ic phase
    constexpr unsigned W_STEPB = 576u * 4u;           // 2304 B per phase

    __shared__ __align__(16) float smem[2 * BUF_FL];  // 25.7 KB

    const int b = blockIdx.y;
    const int tx = blockIdx.x % TX, ty = blockIdx.x / TX;
    const int ox0t = tx * 16, oy0 = ty * 16;
    const int ix0 = 2 * ox0t, iy0 = 2 * oy0;
    const float* in = (L == 0) ? g_buf1 : (L == 1) ? g_buf2 : (L == 2) ? g_buf3 : g_buf4;
    float* out = (L == 0) ? g_buf2 : (L == 1) ? g_buf3 : (L == 2) ? g_buf4 : g_buf5;
    const char* inb8 = (const char*)(in + (size_t)b * 32 * IH * IWS);
    const char* wt8 = (const char*)(g_wtl + L * 9216);

    // fill slots: 5 input (2 ic x 33 rows x 9 = 594 float4) + 2 weight (144)
    unsigned in_src[5], in_dst[5], w_src[2], w_dst[2];
    bool vin[5], vw[2];
#pragma unroll
    for (int k = 0; k < 5; k++) {
        int s = threadIdx.x + k * 128;
        vin[k] = (s < 594);
        s = min(s, 593);
        int ic = s / 297, r = s - ic * 297;
        int row = r / 9, xq = r - row * 9;
        int gy = min(iy0 + row, IH - 1);
        int half = (xq < 5) ? ((ix0 >> 1) + 4 * xq) : (IE + (ix0 >> 1) + 4 * (xq - 5));
        in_src[k] = (unsigned)((ic * IH + gy) * IWS + half) * 4u;
        in_dst[k] = (unsigned)(ic * 1320 + row * 40 + ((xq < 5) ? 4 * xq : 20 + 4 * (xq - 5))) * 4u;
    }
#pragma unroll
    for (int k = 0; k < 2; k++) {
        int idx = threadIdx.x + k * 128;
        vw[k] = (idx < 144);
        idx = min(idx, 143);
        w_src[k] = (unsigned)idx * 16u;
        w_dst[k] = (unsigned)(SW_FL * 4) + (unsigned)idx * 16u;
    }
    const uint32_t sb = smem_u32(smem);

    const int xg = threadIdx.x & 3;
    const int y = (threadIdx.x >> 2) & 15;
    const int g = threadIdx.x >> 6; // 0..1, 16 oc each (warps 0-1: g0; 2-3: g1)
    unsigned long long acc[32];
#pragma unroll
    for (int i = 0; i < 32; i++) acc[i] = 0ULL;

    // prologue fill(0)
    {
        uint32_t base = sb;
#pragma unroll
        for (int k = 0; k < 5; k++) if (vin[k]) cp16(base + in_dst[k], inb8 + in_src[k]);
#pragma unroll
        for (int k = 0; k < 2; k++) if (vw[k]) cp16(base + w_dst[k], wt8 + w_src[k]);
        asm volatile("cp.async.commit_group;");
    }

    for (int ph = 0; ph < 16; ph++) {
        if (ph < 15) {
            uint32_t base = sb + (unsigned)((ph + 1) & 1) * BUF_B;
            unsigned io = (unsigned)(ph + 1) * IN_STEPB;
            unsigned wo = (unsigned)(ph + 1) * W_STEPB;
#pragma unroll
            for (int k = 0; k < 5; k++) if (vin[k]) cp16(base + in_dst[k], inb8 + in_src[k] + io);
#pragma unroll
            for (int k = 0; k < 2; k++) if (vw[k]) cp16(base + w_dst[k], wt8 + w_src[k] + wo);
            asm volatile("cp.async.commit_group;");
            asm volatile("cp.async.wait_group 1;");
        } else {
            asm volatile("cp.async.wait_group 0;");
        }
        __syncthreads();

        const float* sbf = smem + (ph & 1) * BUF_FL;
        const float* pw0 = sbf + SW_FL + g * 16;
#pragma unroll
        for (int ic = 0; ic < 2; ic++) {
            const float* prb = sbf + ic * 1320 + (2 * y) * 40 + 4 * xg;
            const float* pw1 = pw0 + ic * 288;
#pragma unroll
            for (int kh = 0; kh < 3; kh++) {
                const float* pr = prb + kh * 40;
                float4 ev = *reinterpret_cast<const float4*>(pr);
                float e4 = pr[4];
                float4 od = *reinterpret_cast<const float4*>(pr + 20);
                conv_row_taps16(acc, ev, e4, od, pw1 + kh * 96);
            }
        }
        __syncthreads(); // readers done before this buffer is refilled
    }

    const int oy = oy0 + y;
    const int ox0 = ox0t + 4 * xg;
    // ox0 < OWS is load-bearing (R8 bug): masks lanes that would clobber
    // odd-half/next-row data on the 7-wide layer.
    if (oy < OH && ox0 < OWS) {
        const float* bns = g_bns + (L + 1) * 32;
        const float* bsh = g_bsh + (L + 1) * 32;
        float* op = out + ((size_t)b * 32 + g * 16) * (OH * OWS) + (size_t)oy * OWS + (ox0 >> 1);
#pragma unroll
        for (int j = 0; j < 8; j++) {
            int oc0 = g * 16 + 2 * j;
            float bi0 = bias[oc0], sc0 = bns[oc0], sh0 = bsh[oc0];
            float bi1 = bias[oc0 + 1], sc1 = bns[oc0 + 1], sh1 = bsh[oc0 + 1];
            float t0 = fmaxf(lo32(acc[0 + j]) + bi0, 0.f) * sc0 + sh0;   // x+0 even
            float t1 = fmaxf(lo32(acc[8 + j]) + bi0, 0.f) * sc0 + sh0;   // x+1 odd
            float t2 = fmaxf(lo32(acc[16 + j]) + bi0, 0.f) * sc0 + sh0;  // x+2 even
            float t3 = fmaxf(lo32(acc[24 + j]) + bi0, 0.f) * sc0 + sh0;  // x+3 odd
            float u0 = fmaxf(hi32(acc[0 + j]) + bi1, 0.f) * sc1 + sh1;
            float u1 = fmaxf(hi32(acc[8 + j]) + bi1, 0.f) * sc1 + sh1;
            float u2 = fmaxf(hi32(acc[16 + j]) + bi1, 0.f) * sc1 + sh1;
            float u3 = fmaxf(hi32(acc[24 + j]) + bi1, 0.f) * sc1 + sh1;
            float* p0 = op + (size_t)(2 * j) * (OH * OWS);
            float* p1 = op + (size_t)(2 * j + 1) * (OH * OWS);
            *reinterpret_cast<float2*>(p0) = make_float2(t0, t2);
            *reinterpret_cast<float2*>(p0 + OE) = make_float2(t1, t3);
            *reinterpret_cast<float2*>(p1) = make_float2(u0, u2);
            *reinterpret_cast<float2*>(p1 + OE) = make_float2(u1, u3);
        }
    }
}

// ---------------------------------------------------------------------------
// FC(1568->20 relu) -> FC(20->10) -> Thomas tridiagonal solve (fp64) -> a,b,c.
// buf5 rows are even/odd-split: (row,x) -> row*8 + (x&1 ? 4+x/2 : x/2).
// ---------------------------------------------------------------------------
__global__ void __launch_bounds__(256) fc_kernel(const float* __restrict__ l1w,
                                                 const float* __restrict__ l1b,
                                                 const float* __restrict__ l2w,
                                                 const float* __restrict__ l2b) {
    __shared__ float s_y[1568];
    __shared__ float s_h1[20];
    __shared__ float s_ys[10];
    const int b = blockIdx.x;
    const float* yb = g_buf5 + (size_t)b * 32 * 7 * 8;
    for (int i = threadIdx.x; i < 1568; i += 256) {
        int oc = i / 49, r = i % 49;
        int row = r / 7, x = r - row * 7;
        int pos = row * 8 + ((x & 1) ? 4 + (x >> 1) : (x >> 1));
        s_y[i] = yb[oc * 56 + pos];
    }
    __syncthreads();

    const int warp = threadIdx.x >> 5, lane = threadIdx.x & 31;
    for (int j = warp; j < 20; j += 8) {
        float s = 0.f;
        const float* w = l1w + (size_t)j * 1568;
        for (int k = lane; k < 1568; k += 32) s += s_y[k] * w[k];
#pragma unroll
        for (int o = 16; o > 0; o >>= 1) s += __shfl_down_sync(0xffffffffu, s, o);
        if (lane == 0) s_h1[j] = fmaxf(s + l1b[j], 0.f);
    }
    __syncthreads();

    if (threadIdx.x < 10) {
        float s = l2b[threadIdx.x];
        const float* w = l2w + threadIdx.x * 20;
#pragma unroll
        for (int j = 0; j < 20; j++) s += s_h1[j] * w[j];
        s_ys[threadIdx.x] = s;
    }
    __syncthreads();

    if (threadIdx.x == 0) {
        const double h = 1.0 / 9.0;
        double ys[10];
#pragma unroll
        for (int i = 0; i < 10; i++) ys[i] = (double)s_ys[i];
        double d[8], cp[8];
        for (int i = 0; i < 8; i++)
            d[i] = (6.0 / (h * h)) * (ys[i + 2] - 2.0 * ys[i + 1] + ys[i]);
        cp[0] = 0.25;
        d[0] *= 0.25;
        for (int i = 1; i < 8; i++) {
            double m = 4.0 - cp[i - 1];
            cp[i] = 1.0 / m;
            d[i] = (d[i] - d[i - 1]) / m;
        }
        double M[10];
        M[0] = 0.0;
        M[9] = 0.0;
        M[8] = d[7];
        for (int i = 6; i >= 0; i--) M[i + 1] = d[i] - cp[i] * M[i + 2];
        float* cf = g_coef + b * 27;
        for (int i = 0; i < 9; i++) {
            cf[i] = (float)((M[i + 1] - M[i]) / (6.0 * h));
            cf[9 + i] = (float)(M[i] * 0.5);
            cf[18 + i] = (float)((ys[i + 1] - ys[i]) / h - (M[i + 1] + 2.0 * M[i]) * (h / 6.0));
        }
    }
}

// ---------------------------------------------------------------------------
// eval: fast bucket via x*9; exact __fdiv_rn fallback only near knots.
// ---------------------------------------------------------------------------
__device__ __forceinline__ float evalpix(float x, const float* __restrict__ sc) {
    const float h = 1.0f / 9.0f;
    float tf = fminf(fmaxf(x * 9.0f, 0.f), 8.f);
    int xi = (int)tf;
    float fr = tf - (float)xi;
    if (fr < 1e-4f || fr > 0.9999f) {
        float te = fminf(fmaxf(__fdiv_rn(x, h), 0.f), 8.f);
        xi = (int)te;
    }
    float xf = x - (float)xi * h;
    return ((sc[xi] * xf + sc[9 + xi]) * xf + sc[18 + xi]) * xf;
}

__global__ void __launch_bounds__(256) eval_kernel(const float* __restrict__ in,
                                                   float* __restrict__ out) {
    __shared__ float s_c[27];
    const int b = blockIdx.y;
    if (threadIdx.x < 27) s_c[threadIdx.x] = g_coef[b * 27 + threadIdx.x];
    __syncthreads();
    const int N = 3 * 255 * 255;
    const float* ib = in + (size_t)b * N;
    float* ob = out + (size_t)b * N;
    const int mis = (4 - ((3 * b) & 3)) & 3;
    const int nv = (N - mis) >> 2;
    const float4* iv = reinterpret_cast<const float4*>(ib + mis);
    float4* ov = reinterpret_cast<float4*>(ob + mis);
    for (int v = blockIdx.x * 256 + threadIdx.x; v < nv; v += gridDim.x * 256) {
        float4 x = iv[v];
        float4 r;
        r.x = evalpix(x.x, s_c);
        r.y = evalpix(x.y, s_c);
        r.z = evalpix(x.z, s_c);
        r.w = evalpix(x.w, s_c);
        ov[v] = r;
    }
    const int tail = N - mis - 4 * nv;
    if (blockIdx.x == 0 && threadIdx.x < mis + tail) {
        int t = threadIdx.x;
        int i = (t < mis) ? t : (mis + 4 * nv + (t - mis));
        ob[i] = evalpix(ib[i], s_c);
    }
}

// ---------------------------------------------------------------------------
extern "C" void kernel_launch(void* const* d_in, const int* in_sizes, int n_in,
                              void* d_out, int out_size) {
    const float* batch = (const float*)d_in[0];
    const float* c1w = (const float*)d_in[1];
    const float* c1b = (const float*)d_in[2];
    const float* cw = (const float*)d_in[3];
    const float* cb = (const float*)d_in[4];
    const float* bng = (const float*)d_in[5];
    const float* bnb = (const float*)d_in[6];
    const float* bnm = (const float*)d_in[7];
    const float* bnv = (const float*)d_in[8];
    const float* l1w = (const float*)d_in[9];
    const float* l1b = (const float*)d_in[10];
    const float* l2w = (const float*)d_in[11];
    const float* l2b = (const float*)d_in[12];
    float* out = (float*)d_out;

    prep_kernel<<<64, 256>>>(c1w, cw, bng, bnb, bnm, bnv);
    conv1_kernel<<<dim3(64, 64), 256>>>(batch, c1b);
    //            L  IH  IWS IE  OH  OWS OE  TX
    conv32_kernel<0, 127, 128, 64, 63, 64, 32, 4><<<dim3(16, 64), 128>>>(cb + 0);
    conv32_kernel<1, 63, 64, 32, 31, 32, 16, 2><<<dim3(4, 64), 128>>>(cb + 32);
    conv32_kernel<2, 31, 32, 16, 15, 16, 8, 1><<<dim3(1, 64), 128>>>(cb + 64);
    conv32_kernel<3, 15, 16, 8, 7, 8, 4, 1><<<dim3(1, 64), 128>>>(cb + 96);
    fc_kernel<<<64, 256>>>(l1w, l1b, l2w, l2b);
    eval_kernel<<<dim3(191, 64), 256>>>(batch, out);
}

// round 13
// speedup vs baseline: 1.0856x; 1.0301x over previous
#include <cuda_runtime.h>
#include <cstdint>

// ---------------------------------------------------------------------------
// NeuralSpline R13 = R9 + dedicated conv32<0> kernel (256 thr, 16x16 tile,
// 8oc x 4sp per thread, 2-ic x 16 cp.async phases): combines R9's best
// FFMA2/LDS mix, R12's tile reuse, R10's thread count on the DOMINANT layer.
// conv1 / conv32<1..3> / fc / eval are R9 verbatim.
// ---------------------------------------------------------------------------

#define EPSF 1e-5f

static __device__ __align__(16) float g_buf1[64 * 32 * 127 * 128 + 64];
static __device__ __align__(16) float g_buf2[64 * 32 * 63 * 64 + 64];
static __device__ __align__(16) float g_buf3[64 * 32 * 31 * 32 + 64];
static __device__ __align__(16) float g_buf4[64 * 32 * 15 * 16 + 64];
static __device__ __align__(16) float g_buf5[64 * 32 * 7 * 8 + 64];
static __device__ __align__(16) float g_wt1[27 * 32];
static __device__ __align__(16) float g_wtl[4 * 288 * 32];
static __device__ float g_bns[5 * 32];
static __device__ float g_bsh[5 * 32];
static __device__ float g_coef[64 * 27];

// ---- packed f32x2 helpers ---------------------------------------------------
__device__ __forceinline__ unsigned long long pk2(float x) {
    unsigned long long r;
    unsigned u = __float_as_uint(x);
    asm("mov.b64 %0, {%1, %1};" : "=l"(r) : "r"(u));
    return r;
}
__device__ __forceinline__ void ffma2(unsigned long long& a, unsigned long long x,
                                      unsigned long long w) {
    asm("fma.rn.f32x2 %0, %1, %2, %0;" : "+l"(a) : "l"(x), "l"(w));
}
__device__ __forceinline__ float lo32(unsigned long long v) {
    return __uint_as_float((unsigned)(v & 0xffffffffULL));
}
__device__ __forceinline__ float hi32(unsigned long long v) {
    return __uint_as_float((unsigned)(v >> 32));
}
__device__ __forceinline__ uint32_t smem_u32(const void* p) {
    uint32_t a;
    asm("{ .reg .u64 t; cvta.to.shared.u64 t, %1; cvt.u32.u64 %0, t; }" : "=r"(a) : "l"(p));
    return a;
}
__device__ __forceinline__ void cp16(uint32_t dst, const void* src) {
    asm volatile("cp.async.cg.shared.global [%0], [%1], 16;" :: "r"(dst), "l"(src));
}

// ---------------------------------------------------------------------------
__global__ void prep_kernel(const float* __restrict__ c1w, const float* __restrict__ cw,
                            const float* __restrict__ bng, const float* __restrict__ bnb,
                            const float* __restrict__ bnm, const float* __restrict__ bnv) {
    const int stride = gridDim.x * blockDim.x;
    const int t0 = blockIdx.x * blockDim.x + threadIdx.x;
    for (int i = t0; i < 5 * 32; i += stride) {
        float inv = bng[i] * rsqrtf(bnv[i] + EPSF);
        g_bns[i] = inv;
        g_bsh[i] = bnb[i] - bnm[i] * inv;
    }
    for (int i = t0; i < 27 * 32; i += stride) {
        int oc = i / 27, r = i % 27;
        g_wt1[r * 32 + oc] = c1w[i];
    }
    for (int i = t0; i < 4 * 32 * 288; i += stride) {
        int l = i / 9216, rem = i % 9216;
        int oc = rem / 288, r = rem % 288;
        g_wtl[l * 9216 + r * 32 + oc] = cw[i];
    }
}

// 48 FFMA2 per (ic,kh) row unit, 8-oc.
__device__ __forceinline__ void conv_row_taps8(unsigned long long (&acc)[16],
                                               const float4 ev, const float e4,
                                               const float4 od,
                                               const float* __restrict__ pw) {
    unsigned long long pe0 = pk2(ev.x), pe1 = pk2(ev.y), pe2 = pk2(ev.z),
                       pe3 = pk2(ev.w), pe4 = pk2(e4);
    unsigned long long po0 = pk2(od.x), po1 = pk2(od.y), po2 = pk2(od.z), po3 = pk2(od.w);
#pragma unroll
    for (int kw = 0; kw < 3; kw++) {
        unsigned long long x0, x1, x2, x3;
        if (kw == 0) { x0 = pe0; x1 = pe1; x2 = pe2; x3 = pe3; }
        else if (kw == 1) { x0 = po0; x1 = po1; x2 = po2; x3 = po3; }
        else { x0 = pe1; x1 = pe2; x2 = pe3; x3 = pe4; }
        const ulonglong2* w2 = reinterpret_cast<const ulonglong2*>(pw + kw * 32);
        ulonglong2 wa = w2[0], wb = w2[1];
        ffma2(acc[0], x0, wa.x);  ffma2(acc[1], x0, wa.y);
        ffma2(acc[2], x0, wb.x);  ffma2(acc[3], x0, wb.y);
        ffma2(acc[4], x1, wa.x);  ffma2(acc[5], x1, wa.y);
        ffma2(acc[6], x1, wb.x);  ffma2(acc[7], x1, wb.y);
        ffma2(acc[8], x2, wa.x);  ffma2(acc[9], x2, wa.y);
        ffma2(acc[10], x2, wb.x); ffma2(acc[11], x2, wb.y);
        ffma2(acc[12], x3, wa.x); ffma2(acc[13], x3, wa.y);
        ffma2(acc[14], x3, wb.x); ffma2(acc[15], x3, wb.y);
    }
}

// Epilogue: bias+relu+BN; write even/odd-split rows (2x STG.64 per oc).
template <int PLANE, int OE>
__device__ __forceinline__ void conv_store8(const unsigned long long (&acc)[16],
                                            float* __restrict__ op,
                                            const float* __restrict__ bias,
                                            const float* __restrict__ bns,
                                            const float* __restrict__ bsh, int ocbase) {
#pragma unroll
    for (int j = 0; j < 4; j++) {
        int oc0 = ocbase + 2 * j;
        float bi0 = bias[oc0], sc0 = bns[oc0], sh0 = bsh[oc0];
        float bi1 = bias[oc0 + 1], sc1 = bns[oc0 + 1], sh1 = bsh[oc0 + 1];
        float t0 = fmaxf(lo32(acc[0 + j]) + bi0, 0.f) * sc0 + sh0;  // x+0 even
        float t1 = fmaxf(lo32(acc[4 + j]) + bi0, 0.f) * sc0 + sh0;  // x+1 odd
        float t2 = fmaxf(lo32(acc[8 + j]) + bi0, 0.f) * sc0 + sh0;  // x+2 even
        float t3 = fmaxf(lo32(acc[12 + j]) + bi0, 0.f) * sc0 + sh0; // x+3 odd
        float u0 = fmaxf(hi32(acc[0 + j]) + bi1, 0.f) * sc1 + sh1;
        float u1 = fmaxf(hi32(acc[4 + j]) + bi1, 0.f) * sc1 + sh1;
        float u2 = fmaxf(hi32(acc[8 + j]) + bi1, 0.f) * sc1 + sh1;
        float u3 = fmaxf(hi32(acc[12 + j]) + bi1, 0.f) * sc1 + sh1;
        float* p0 = op + (size_t)(2 * j) * PLANE;
        float* p1 = op + (size_t)(2 * j + 1) * PLANE;
        *reinterpret_cast<float2*>(p0) = make_float2(t0, t2);
        *reinterpret_cast<float2*>(p0 + OE) = make_float2(t1, t3);
        *reinterpret_cast<float2*>(p1) = make_float2(u0, u2);
        *reinterpret_cast<float2*>(p1 + OE) = make_float2(u1, u3);
    }
}

// ---------------------------------------------------------------------------
// conv1: 3 -> 32 ch, 255x255 -> 127 x (64e|63o).  16x16 tile, 256 thr (R9).
// ---------------------------------------------------------------------------
__global__ void __launch_bounds__(256) conv1_kernel(const float* __restrict__ in,
                                                    const float* __restrict__ bias) {
    __shared__ __align__(16) float s_in[3 * 33 * 40];
    __shared__ __align__(16) float s_w[27 * 32];
    const int b = blockIdx.y;
    const int tx = blockIdx.x & 7, ty = blockIdx.x >> 3;
    const int ox0t = tx * 16, oy0 = ty * 16;
    const int ix0 = 2 * ox0t, iy0 = 2 * oy0;

    if (threadIdx.x < 216)
        reinterpret_cast<float4*>(s_w)[threadIdx.x] =
            reinterpret_cast<const float4*>(g_wt1)[threadIdx.x];

    const float* inb = in + (size_t)b * 3 * 65025;
    int goff[5], soff[5];
#pragma unroll
    for (int k = 0; k < 5; k++) {
        int s = threadIdx.x + k * 256;
        s = min(s, 1088);
        int yy = s / 33, xx = s - yy * 33;
        int gy = min(iy0 + yy, 254), gx = min(ix0 + xx, 254);
        goff[k] = gy * 255 + gx;
        soff[k] = yy * 40 + ((xx & 1) ? 20 + (xx >> 1) : (xx >> 1));
    }
#pragma unroll
    for (int ic = 0; ic < 3; ic++) {
        float v[5];
#pragma unroll
        for (int k = 0; k < 5; k++) v[k] = inb[ic * 65025 + goff[k]];
#pragma unroll
        for (int k = 0; k < 5; k++) s_in[ic * 1320 + soff[k]] = v[k];
    }
    __syncthreads();

    const int xg = threadIdx.x & 3;
    const int y = (threadIdx.x >> 2) & 15;
    const int g = threadIdx.x >> 6;
    unsigned long long acc[16];
#pragma unroll
    for (int i = 0; i < 16; i++) acc[i] = 0ULL;

    const float* pw0 = s_w + g * 8;
#pragma unroll
    for (int ic = 0; ic < 3; ic++) {
        const float* prb = s_in + ic * 1320 + (2 * y) * 40 + 4 * xg;
#pragma unroll
        for (int kh = 0; kh < 3; kh++) {
            const float* pr = prb + kh * 40;
            float4 ev = *reinterpret_cast<const float4*>(pr);
            float e4 = pr[4];
            float4 od = *reinterpret_cast<const float4*>(pr + 20);
            conv_row_taps8(acc, ev, e4, od, pw0 + (ic * 9 + kh * 3) * 32);
        }
    }

    const int oy = oy0 + y;
    const int ox0 = ox0t + 4 * xg;
    if (oy < 127 && ox0 < 128) {
        float* op = g_buf1 + ((size_t)b * 32 + g * 8) * (127 * 128) + (size_t)oy * 128 + (ox0 >> 1);
        conv_store8<127 * 128, 64>(acc, op, bias, g_bns, g_bsh, g * 8);
    }
}

// ---------------------------------------------------------------------------
// conv32<0> (DOMINANT layer): 127 -> 63.  256 thr (xg4 x y16 x g4), 16x16
// tile, 8oc x 4sp per thread, 2-ic x 16 phases, cp.async double-buffer.
// ---------------------------------------------------------------------------
__global__ void __launch_bounds__(256) conv32a_kernel(const float* __restrict__ bias) {
    constexpr int IH = 127, IWS = 128, IE = 64, OH = 63, OWS = 64, OE = 32, TX = 4;
    constexpr int SW_FL = 2 * 1320;           // 2 ic x 33 rows x 40
    constexpr int BUF_FL = SW_FL + 576;       // + weights (2 ic x 288) = 3216
    constexpr unsigned BUF_B = BUF_FL * 4u;
    constexpr unsigned IN_STEPB = 2u * IH * IWS * 4u;
    constexpr unsigned W_STEPB = 576u * 4u;

    __shared__ __align__(16) float smem[2 * BUF_FL];  // 25.7 KB

    const int b = blockIdx.y;
    const int tx = blockIdx.x % TX, ty = blockIdx.x / TX;
    const int ox0t = tx * 16, oy0 = ty * 16;
    const int ix0 = 2 * ox0t, iy0 = 2 * oy0;
    const char* inb8 = (const char*)(g_buf1 + (size_t)b * 32 * IH * IWS);
    const char* wt8 = (const char*)(g_wtl); // L=0

    // fill slots: 3 input (594 float4 over 256 thr) + 1 weight (144 float4)
    unsigned in_src[3], in_dst[3], w_src1, w_dst1;
    bool vin[3], vw1;
#pragma unroll
    for (int k = 0; k < 3; k++) {
        int s = threadIdx.x + k * 256;
        vin[k] = (s < 594);
        s = min(s, 593);
        int ic = s / 297, r = s - ic * 297;
        int row = r / 9, xq = r - row * 9;
        int gy = min(iy0 + row, IH - 1);
        int half = (xq < 5) ? ((ix0 >> 1) + 4 * xq) : (IE + (ix0 >> 1) + 4 * (xq - 5));
        in_src[k] = (unsigned)((ic * IH + gy) * IWS + half) * 4u;
        in_dst[k] = (unsigned)(ic * 1320 + row * 40 + ((xq < 5) ? 4 * xq : 20 + 4 * (xq - 5))) * 4u;
    }
    {
        int idx = threadIdx.x;
        vw1 = (idx < 144);
        idx = min(idx, 143);
        w_src1 = (unsigned)idx * 16u;
        w_dst1 = (unsigned)(SW_FL * 4) + (unsigned)idx * 16u;
    }
    const uint32_t sb = smem_u32(smem);

    const int xg = threadIdx.x & 3;
    const int y = (threadIdx.x >> 2) & 15;
    const int g = threadIdx.x >> 6; // 0..3, 8 oc each
    unsigned long long acc[16];
#pragma unroll
    for (int i = 0; i < 16; i++) acc[i] = 0ULL;

    // prologue fill(0)
    {
        uint32_t base = sb;
#pragma unroll
        for (int k = 0; k < 3; k++) if (vin[k]) cp16(base + in_dst[k], inb8 + in_src[k]);
        if (vw1) cp16(base + w_dst1, wt8 + w_src1);
        asm volatile("cp.async.commit_group;");
    }

    for (int ph = 0; ph < 16; ph++) {
        if (ph < 15) {
            uint32_t base = sb + (unsigned)((ph + 1) & 1) * BUF_B;
            unsigned io = (unsigned)(ph + 1) * IN_STEPB;
            unsigned wo = (unsigned)(ph + 1) * W_STEPB;
#pragma unroll
            for (int k = 0; k < 3; k++) if (vin[k]) cp16(base + in_dst[k], inb8 + in_src[k] + io);
            if (vw1) cp16(base + w_dst1, wt8 + w_src1 + wo);
            asm volatile("cp.async.commit_group;");
            asm volatile("cp.async.wait_group 1;");
        } else {
            asm volatile("cp.async.wait_group 0;");
        }
        __syncthreads();

        const float* sbf = smem + (ph & 1) * BUF_FL;
        const float* pw0 = sbf + SW_FL + g * 8;
#pragma unroll
        for (int ic = 0; ic < 2; ic++) {
            const float* prb = sbf + ic * 1320 + (2 * y) * 40 + 4 * xg;
            const float* pw1 = pw0 + ic * 288;
#pragma unroll
            for (int kh = 0; kh < 3; kh++) {
                const float* pr = prb + kh * 40;
                float4 ev = *reinterpret_cast<const float4*>(pr);
                float e4 = pr[4];
                float4 od = *reinterpret_cast<const float4*>(pr + 20);
                conv_row_taps8(acc, ev, e4, od, pw1 + kh * 96);
            }
        }
        __syncthreads(); // readers done before this buffer is refilled
    }

    const int oy = oy0 + y;
    const int ox0 = ox0t + 4 * xg;
    if (oy < OH && ox0 < OWS) {
        const float* bns = g_bns + 1 * 32;
        const float* bsh = g_bsh + 1 * 32;
        float* op = g_buf2 + ((size_t)b * 32 + g * 8) * (OH * OWS) + (size_t)oy * OWS + (ox0 >> 1);
        conv_store8<OH * OWS, OE>(acc, op, bias, bns, bsh, g * 8);
    }
}

// ---------------------------------------------------------------------------
// conv32<1..3>: R9 verbatim.  128 thr (xg4 x y8 x g4), 16x8 tile, 4-ic x 8
// phases, cp.async double-buffered fill.
// ---------------------------------------------------------------------------
template <int L, int IH, int IWS, int IE, int OH, int OWS, int OE, int TX>
__global__ void __launch_bounds__(128) conv32_kernel(const float* __restrict__ bias) {
    constexpr int SW_FL = 4 * 680;
    constexpr int BUF_FL = SW_FL + 1152;
    constexpr unsigned BUF_B = BUF_FL * 4u;
    constexpr unsigned IN_STEPB = 4u * IH * IWS * 4u;

    __shared__ __align__(16) float smem[2 * BUF_FL];

    const int b = blockIdx.y;
    const int tx = blockIdx.x % TX, ty = blockIdx.x / TX;
    const int ox0t = tx * 16, oy0 = ty * 8;
    const int ix0 = 2 * ox0t, iy0 = 2 * oy0;
    const float* in = (L == 1) ? g_buf2 : (L == 2) ? g_buf3 : g_buf4;
    float* out = (L == 1) ? g_buf3 : (L == 2) ? g_buf4 : g_buf5;
    const char* inb8 = (const char*)(in + (size_t)b * 32 * IH * IWS);
    const char* wt8 = (const char*)(g_wtl + L * 9216);

    unsigned in_src[5], in_dst[5], w_src[3], w_dst[3];
    bool vin[5], vw[3];
#pragma unroll
    for (int k = 0; k < 5; k++) {
        int s = threadIdx.x + k * 128;
        vin[k] = (s < 612);
        s = min(s, 611);
        int ic = s / 153, r = s - ic * 153;
        int row = r / 9, xq = r - row * 9;
        int gy = min(iy0 + row, IH - 1);
        int half = (xq < 5) ? ((ix0 >> 1) + 4 * xq) : (IE + (ix0 >> 1) + 4 * (xq - 5));
        in_src[k] = (unsigned)((ic * IH + gy) * IWS + half) * 4u;
        in_dst[k] = (unsigned)(ic * 680 + row * 40 + ((xq < 5) ? 4 * xq : 20 + 4 * (xq - 5))) * 4u;
    }
#pragma unroll
    for (int k = 0; k < 3; k++) {
        int idx = threadIdx.x + k * 128;
        vw[k] = (idx < 288);
        idx = min(idx, 287);
        w_src[k] = (unsigned)idx * 16u;
        w_dst[k] = (unsigned)(SW_FL * 4) + (unsigned)idx * 16u;
    }
    const uint32_t sb = smem_u32(smem);

    const int xg = threadIdx.x & 3;
    const int y = (threadIdx.x >> 2) & 7;
    const int g = threadIdx.x >> 5;
    unsigned long long acc[16];
#pragma unroll
    for (int i = 0; i < 16; i++) acc[i] = 0ULL;

    {
        uint32_t base = sb;
#pragma unroll
        for (int k = 0; k < 5; k++) if (vin[k]) cp16(base + in_dst[k], inb8 + in_src[k]);
#pragma unroll
        for (int k = 0; k < 3; k++) if (vw[k]) cp16(base + w_dst[k], wt8 + w_src[k]);
        asm volatile("cp.async.commit_group;");
    }

    for (int ph = 0; ph < 8; ph++) {
        if (ph < 7) {
            uint32_t base = sb + (unsigned)((ph + 1) & 1) * BUF_B;
            unsigned io = (unsigned)(ph + 1) * IN_STEPB;
            unsigned wo = (unsigned)(ph + 1) * 4608u;
#pragma unroll
            for (int k = 0; k < 5; k++) if (vin[k]) cp16(base + in_dst[k], inb8 + in_src[k] + io);
#pragma unroll
            for (int k = 0; k < 3; k++) if (vw[k]) cp16(base + w_dst[k], wt8 + w_src[k] + wo);
            asm volatile("cp.async.commit_group;");
            asm volatile("cp.async.wait_group 1;");
        } else {
            asm volatile("cp.async.wait_group 0;");
        }
        __syncthreads();

        const float* sbf = smem + (ph & 1) * BUF_FL;
        const float* pw0 = sbf + SW_FL + g * 8;
#pragma unroll
        for (int ic = 0; ic < 4; ic++) {
            const float* prb = sbf + ic * 680 + (2 * y) * 40 + 4 * xg;
            const float* pw1 = pw0 + ic * 288;
#pragma unroll
            for (int kh = 0; kh < 3; kh++) {
                const float* pr = prb + kh * 40;
                float4 ev = *reinterpret_cast<const float4*>(pr);
                float e4 = pr[4];
                float4 od = *reinterpret_cast<const float4*>(pr + 20);
                conv_row_taps8(acc, ev, e4, od, pw1 + kh * 96);
            }
        }
        __syncthreads();
    }

    const int oy = oy0 + y;
    const int ox0 = ox0t + 4 * xg;
    // ox0 < OWS is load-bearing (the R8 corruption bug).
    if (oy < OH && ox0 < OWS) {
        const float* bns = g_bns + (L + 1) * 32;
        const float* bsh = g_bsh + (L + 1) * 32;
        float* op = out + ((size_t)b * 32 + g * 8) * (OH * OWS) + (size_t)oy * OWS + (ox0 >> 1);
        conv_store8<OH * OWS, OE>(acc, op, bias, bns, bsh, g * 8);
    }
}

// ---------------------------------------------------------------------------
// FC + spline solve (R9 verbatim).
// ---------------------------------------------------------------------------
__global__ void __launch_bounds__(256) fc_kernel(const float* __restrict__ l1w,
                                                 const float* __restrict__ l1b,
                                                 const float* __restrict__ l2w,
                                                 const float* __restrict__ l2b) {
    __shared__ float s_y[1568];
    __shared__ float s_h1[20];
    __shared__ float s_ys[10];
    const int b = blockIdx.x;
    const float* yb = g_buf5 + (size_t)b * 32 * 7 * 8;
    for (int i = threadIdx.x; i < 1568; i += 256) {
        int oc = i / 49, r = i % 49;
        int row = r / 7, x = r - row * 7;
        int pos = row * 8 + ((x & 1) ? 4 + (x >> 1) : (x >> 1));
        s_y[i] = yb[oc * 56 + pos];
    }
    __syncthreads();

    const int warp = threadIdx.x >> 5, lane = threadIdx.x & 31;
    for (int j = warp; j < 20; j += 8) {
        float s = 0.f;
        const float* w = l1w + (size_t)j * 1568;
        for (int k = lane; k < 1568; k += 32) s += s_y[k] * w[k];
#pragma unroll
        for (int o = 16; o > 0; o >>= 1) s += __shfl_down_sync(0xffffffffu, s, o);
        if (lane == 0) s_h1[j] = fmaxf(s + l1b[j], 0.f);
    }
    __syncthreads();

    if (threadIdx.x < 10) {
        float s = l2b[threadIdx.x];
        const float* w = l2w + threadIdx.x * 20;
#pragma unroll
        for (int j = 0; j < 20; j++) s += s_h1[j] * w[j];
        s_ys[threadIdx.x] = s;
    }
    __syncthreads();

    if (threadIdx.x == 0) {
        const double h = 1.0 / 9.0;
        double ys[10];
#pragma unroll
        for (int i = 0; i < 10; i++) ys[i] = (double)s_ys[i];
        double d[8], cp[8];
        for (int i = 0; i < 8; i++)
            d[i] = (6.0 / (h * h)) * (ys[i + 2] - 2.0 * ys[i + 1] + ys[i]);
        cp[0] = 0.25;
        d[0] *= 0.25;
        for (int i = 1; i < 8; i++) {
            double m = 4.0 - cp[i - 1];
            cp[i] = 1.0 / m;
            d[i] = (d[i] - d[i - 1]) / m;
        }
        double M[10];
        M[0] = 0.0;
        M[9] = 0.0;
        M[8] = d[7];
        for (int i = 6; i >= 0; i--) M[i + 1] = d[i] - cp[i] * M[i + 2];
        float* cf = g_coef + b * 27;
        for (int i = 0; i < 9; i++) {
            cf[i] = (float)((M[i + 1] - M[i]) / (6.0 * h));
            cf[9 + i] = (float)(M[i] * 0.5);
            cf[18 + i] = (float)((ys[i + 1] - ys[i]) / h - (M[i + 1] + 2.0 * M[i]) * (h / 6.0));
        }
    }
}

// ---------------------------------------------------------------------------
// eval (R9 verbatim): fast bucket via x*9; exact __fdiv_rn fallback near knots.
// ---------------------------------------------------------------------------
__device__ __forceinline__ float evalpix(float x, const float* __restrict__ sc) {
    const float h = 1.0f / 9.0f;
    float tf = fminf(fmaxf(x * 9.0f, 0.f), 8.f);
    int xi = (int)tf;
    float fr = tf - (float)xi;
    if (fr < 1e-4f || fr > 0.9999f) {
        float te = fminf(fmaxf(__fdiv_rn(x, h), 0.f), 8.f);
        xi = (int)te;
    }
    float xf = x - (float)xi * h;
    return ((sc[xi] * xf + sc[9 + xi]) * xf + sc[18 + xi]) * xf;
}

__global__ void __launch_bounds__(256) eval_kernel(const float* __restrict__ in,
                                                   float* __restrict__ out) {
    __shared__ float s_c[27];
    const int b = blockIdx.y;
    if (threadIdx.x < 27) s_c[threadIdx.x] = g_coef[b * 27 + threadIdx.x];
    __syncthreads();
    const int N = 3 * 255 * 255;
    const float* ib = in + (size_t)b * N;
    float* ob = out + (size_t)b * N;
    const int mis = (4 - ((3 * b) & 3)) & 3;
    const int nv = (N - mis) >> 2;
    const float4* iv = reinterpret_cast<const float4*>(ib + mis);
    float4* ov = reinterpret_cast<float4*>(ob + mis);
    for (int v = blockIdx.x * 256 + threadIdx.x; v < nv; v += gridDim.x * 256) {
        float4 x = iv[v];
        float4 r;
        r.x = evalpix(x.x, s_c);
        r.y = evalpix(x.y, s_c);
        r.z = evalpix(x.z, s_c);
        r.w = evalpix(x.w, s_c);
        ov[v] = r;
    }
    const int tail = N - mis - 4 * nv;
    if (blockIdx.x == 0 && threadIdx.x < mis + tail) {
        int t = threadIdx.x;
        int i = (t < mis) ? t : (mis + 4 * nv + (t - mis));
        ob[i] = evalpix(ib[i], s_c);
    }
}

// ---------------------------------------------------------------------------
extern "C" void kernel_launch(void* const* d_in, const int* in_sizes, int n_in,
                              void* d_out, int out_size) {
    const float* batch = (const float*)d_in[0];
    const float* c1w = (const float*)d_in[1];
    const float* c1b = (const float*)d_in[2];
    const float* cw = (const float*)d_in[3];
    const float* cb = (const float*)d_in[4];
    const float* bng = (const float*)d_in[5];
    const float* bnb = (const float*)d_in[6];
    const float* bnm = (const float*)d_in[7];
    const float* bnv = (const float*)d_in[8];
    const float* l1w = (const float*)d_in[9];
    const float* l1b = (const float*)d_in[10];
    const float* l2w = (const float*)d_in[11];
    const float* l2b = (const float*)d_in[12];
    float* out = (float*)d_out;

    prep_kernel<<<64, 256>>>(c1w, cw, bng, bnb, bnm, bnv);
    conv1_kernel<<<dim3(64, 64), 256>>>(batch, c1b);
    conv32a_kernel<<<dim3(16, 64), 256>>>(cb + 0); // 127->63, 16x16 tiles
    //            L  IH  IWS IE  OH  OWS OE  TX
    conv32_kernel<1, 63, 64, 32, 31, 32, 16, 2><<<dim3(8, 64), 128>>>(cb + 32);
    conv32_kernel<2, 31, 32, 16, 15, 16, 8, 1><<<dim3(2, 64), 128>>>(cb + 64);
    conv32_kernel<3, 15, 16, 8, 7, 8, 4, 1><<<dim3(1, 64), 128>>>(cb + 96);
    fc_kernel<<<64, 256>>>(l1w, l1b, l2w, l2b);
    eval_kernel<<<dim3(191, 64), 256>>>(batch, out);
}